// round 4
// baseline (speedup 1.0000x reference)
#include <cuda_runtime.h>
#include <cuda_bf16.h>
#include <cstdint>

// Problem dims
#define TB 64      // batch
#define FF 256     // features per stream
#define TT 512     // sequence length
#define SPD 512    // spatial size (2F)
#define HH 1024    // hidden
#define G4 4096    // 4 gates * H

// ---------------- device scratch (static globals; no allocations) ----------------
__device__ float g_xin[TT * TB * SPD];          // 67 MB  : [t][b][k] interleaved x/y_prev, tf32-rounded
__device__ float g_Wx [SPD * G4];               // 8.4 MB : [k][g*1024+n], tf32-rounded
__device__ float g_Wh [HH * G4];                // 16.8MB : packed [j(128)][k(1024)][32=(g*8+r)], tf32-rounded
__device__ float g_b4 [G4];                     // bias   : [g*1024+n]
__device__ float g_gx [(size_t)TT * TB * G4];   // 536MB  : [t*64+b][g*1024+n] = xin@Wx + b
__device__ float g_h0 [TB * HH];                // ping-pong h state (tf32-rounded)
__device__ float g_h1 [TB * HH];
__device__ float g_c  [TB * HH];                // c state (fp32)

// Round fp32 -> tf32 precision (exactly what tcgen05 kind::tf32 does to operands).
// NOTE: tf32 destination must be a .b32 register in PTX, hence "=r".
__device__ __forceinline__ float tf32r(float v) {
    uint32_t r;
    asm("cvt.rna.tf32.f32 %0, %1;" : "=r"(r) : "f"(v));
    return __uint_as_float(r);
}
__device__ __forceinline__ float sigf(float x) {
    return 1.0f / (1.0f + __expf(-x));
}

// ---------------- P0a: build interleaved input [t][b][2f]=x, [2f+1]=y_prev ----------------
__global__ __launch_bounds__(256) void prep_xin(const float* __restrict__ x,
                                                const float* __restrict__ y) {
    int idx = blockIdx.x * 256 + threadIdx.x;       // (t*TB + b)*FF + f, f fastest
    if (idx >= TT * TB * FF) return;
    int f = idx % FF;
    int b = (idx / FF) % TB;
    int t = idx / (FF * TB);
    float xv = tf32r(x[(size_t)(b * FF + f) * TT + t]);
    float yv = (t > 0) ? tf32r(y[(size_t)(b * FF + f) * TT + (t - 1)]) : 0.0f;
    float2* dst = (float2*)&g_xin[(size_t)(t * TB + b) * SPD + 2 * f];
    *dst = make_float2(xv, yv);
}

// ---------------- P0b: pack weights/biases, zero state ----------------
__global__ __launch_bounds__(256) void prep_w(const float* __restrict__ Wf, const float* __restrict__ Wi,
                                              const float* __restrict__ Wu, const float* __restrict__ Wo,
                                              const float* __restrict__ bf_, const float* __restrict__ bi,
                                              const float* __restrict__ bu, const float* __restrict__ bo) {
    int idx = blockIdx.x * 256 + threadIdx.x;   // up to HH*G4 = 4,194,304
    if (idx < HH * G4) {
        int k  = idx >> 12;            // 0..1023 (h-row)
        int c4 = idx & 4095;
        int g  = c4 >> 10;
        int n  = c4 & 1023;
        const float* W = (g == 0) ? Wf : (g == 1) ? Wi : (g == 2) ? Wu : Wo;
        float v = tf32r(W[(size_t)(SPD + k) * HH + n]);
        int j = n >> 3, r = n & 7;
        g_Wh[((size_t)(j << 10) + k) * 32 + (g << 3) + r] = v;
    }
    if (idx < SPD * G4) {
        int k  = idx >> 12;            // 0..511 (x-row)
        int c4 = idx & 4095;
        int g  = c4 >> 10;
        int n  = c4 & 1023;
        const float* W = (g == 0) ? Wf : (g == 1) ? Wi : (g == 2) ? Wu : Wo;
        g_Wx[idx] = tf32r(W[(size_t)k * HH + n]);
    }
    if (idx < G4) {
        int g = idx >> 10, n = idx & 1023;
        const float* bb = (g == 0) ? bf_ : (g == 1) ? bi : (g == 2) ? bu : bo;
        g_b4[idx] = bb[n];
    }
    if (idx < TB * HH) {
        g_h0[idx] = 0.0f;
        g_h1[idx] = 0.0f;
        g_c [idx] = 0.0f;
    }
}

// ---------------- P1: gx = xin @ Wx + b   (M=32768, N=4096, K=512) ----------------
// Tile 64(M) x 128(N), 256 threads, per-thread 4x8 accumulators.
__global__ __launch_bounds__(256) void gemm_x() {
    __shared__ float As[16][68];    // [k][m], padded
    __shared__ float Bs[16][128];   // [k][n]
    const int tx = threadIdx.x;
    const int n0 = blockIdx.x * 128;
    const int m0 = blockIdx.y * 64;     // m-tile == one t (64 batch rows)
    const int m4 = tx >> 4;             // 0..15
    const int n8 = tx & 15;             // 0..15

    float acc[4][8];
#pragma unroll
    for (int i = 0; i < 4; i++)
#pragma unroll
        for (int j = 0; j < 8; j++) acc[i][j] = 0.0f;

    for (int kc = 0; kc < SPD; kc += 16) {
#pragma unroll
        for (int it = 0; it < 4; it++) {
            int i  = tx + it * 256;          // 0..1023
            int rr = i >> 4, kk = i & 15;
            As[kk][rr] = g_xin[(size_t)(m0 + rr) * SPD + kc + kk];
        }
#pragma unroll
        for (int it = 0; it < 8; it++) {
            int i  = tx + it * 256;          // 0..2047
            int kk = i >> 7, nn = i & 127;
            Bs[kk][nn] = g_Wx[(size_t)(kc + kk) * G4 + n0 + nn];
        }
        __syncthreads();
#pragma unroll
        for (int kk = 0; kk < 16; kk++) {
            float av[4], bv[8];
            *(float4*)&av[0] = *(const float4*)&As[kk][m4 * 4];
            *(float4*)&bv[0] = *(const float4*)&Bs[kk][n8 * 8];
            *(float4*)&bv[4] = *(const float4*)&Bs[kk][n8 * 8 + 4];
#pragma unroll
            for (int mi = 0; mi < 4; mi++)
#pragma unroll
                for (int ni = 0; ni < 8; ni++) acc[mi][ni] += av[mi] * bv[ni];
        }
        __syncthreads();
    }

    float bias[8];
    *(float4*)&bias[0] = *(const float4*)&g_b4[n0 + n8 * 8];
    *(float4*)&bias[4] = *(const float4*)&g_b4[n0 + n8 * 8 + 4];
#pragma unroll
    for (int mi = 0; mi < 4; mi++) {
        int row = m0 + m4 * 4 + mi;
        float4 v0 = make_float4(acc[mi][0] + bias[0], acc[mi][1] + bias[1],
                                acc[mi][2] + bias[2], acc[mi][3] + bias[3]);
        float4 v1 = make_float4(acc[mi][4] + bias[4], acc[mi][5] + bias[5],
                                acc[mi][6] + bias[6], acc[mi][7] + bias[7]);
        *(float4*)&g_gx[(size_t)row * G4 + n0 + n8 * 8]     = v0;
        *(float4*)&g_gx[(size_t)row * G4 + n0 + n8 * 8 + 4] = v1;
    }
}

// ---------------- P2: one LSTM step ----------------
// 128 CTAs; CTA j owns h-columns [j*8, j*8+8) for all 4 gates (N'=32), M=64 batch.
// GEMM 64x32xK=1024, then gates + cell update for its 8 columns.
__global__ __launch_bounds__(256) void lstm_step(float* __restrict__ out, int t) {
    __shared__ float As[16][68];     // [k][b]
    __shared__ float Bs[16][32];     // [k][c], c = g*8+r
    __shared__ float Ps[32][65];     // preacts [c][b]

    const float* __restrict__ hin = (t & 1) ? g_h1 : g_h0;
    float* __restrict__ hout      = (t & 1) ? g_h0 : g_h1;

    const int tx = threadIdx.x;
    const int bj = blockIdx.x;               // 0..127
    const int m4 = tx >> 4;                  // 0..15
    const int n2 = tx & 15;                  // 0..15
    const float* wbase = &g_Wh[(size_t)bj * (HH * 32)];

    float acc[4][2];
#pragma unroll
    for (int i = 0; i < 4; i++) { acc[i][0] = 0.0f; acc[i][1] = 0.0f; }

    for (int kc = 0; kc < HH; kc += 16) {
#pragma unroll
        for (int it = 0; it < 4; it++) {
            int i  = tx + it * 256;          // 0..1023
            int b  = i >> 4, kk = i & 15;
            As[kk][b] = hin[b * HH + kc + kk];
        }
#pragma unroll
        for (int it = 0; it < 2; it++) {
            int i = tx + it * 256;           // 0..511
            ((float*)Bs)[i] = wbase[kc * 32 + i];
        }
        __syncthreads();
#pragma unroll
        for (int kk = 0; kk < 16; kk++) {
            float av[4];
            *(float4*)&av[0] = *(const float4*)&As[kk][m4 * 4];
            float2 bv = *(const float2*)&Bs[kk][n2 * 2];
#pragma unroll
            for (int mi = 0; mi < 4; mi++) {
                acc[mi][0] += av[mi] * bv.x;
                acc[mi][1] += av[mi] * bv.y;
            }
        }
        __syncthreads();
    }

    // add gx (bias already folded in), park preacts in smem
#pragma unroll
    for (int ni = 0; ni < 2; ni++) {
        int nl = n2 * 2 + ni;                // 0..31
        int g  = nl >> 3, cr = nl & 7;
        int c4 = (g << 10) + bj * 8 + cr;    // column in 4096-space
#pragma unroll
        for (int mi = 0; mi < 4; mi++) {
            int b = m4 * 4 + mi;
            Ps[nl][b] = acc[mi][ni] + g_gx[(size_t)(t * TB + b) * G4 + c4];
        }
    }
    __syncthreads();

    // cell update: 512 (b, col) pairs over 256 threads
    for (int p = tx; p < 512; p += 256) {
        int cr = p >> 6;                     // 0..7
        int b  = p & 63;
        float f  = sigf(Ps[cr][b]);
        float ii = sigf(Ps[8 + cr][b]);
        float u  = tanhf(Ps[16 + cr][b]);
        float o  = sigf(Ps[24 + cr][b]);
        int col  = bj * 8 + cr;
        int idx  = b * HH + col;
        float cn = g_c[idx] * f + ii * u;
        g_c[idx] = cn;
        float h  = o * tanhf(cn);
        out[(size_t)b * HH * TT + (size_t)col * TT + t] = h;   // out[b][col][t]
        hout[idx] = tf32r(h);                                  // tf32-rounded feedback
        if (t == TT - 1) {
            out[(size_t)TB * HH * TT + idx] = cn;              // c_fin tail
        }
    }
}

// ---------------- launch ----------------
extern "C" void kernel_launch(void* const* d_in, const int* in_sizes, int n_in,
                              void* d_out, int out_size) {
    const float* x   = (const float*)d_in[0];
    const float* y   = (const float*)d_in[1];
    // d_in[2] = subject_id (unused; embedding ignored in 'none' mode)
    const float* Wf  = (const float*)d_in[3];
    const float* bf_ = (const float*)d_in[4];
    const float* Wi  = (const float*)d_in[5];
    const float* bi  = (const float*)d_in[6];
    const float* Wu  = (const float*)d_in[7];
    const float* bu  = (const float*)d_in[8];
    const float* Wo  = (const float*)d_in[9];
    const float* bo  = (const float*)d_in[10];
    float* out = (float*)d_out;

    prep_xin<<<(TT * TB * FF) / 256, 256>>>(x, y);
    prep_w<<<(HH * G4) / 256, 256>>>(Wf, Wi, Wu, Wo, bf_, bi, bu, bo);
    gemm_x<<<dim3(G4 / 128, (TT * TB) / 64), 256>>>();
    for (int t = 0; t < TT; t++) {
        lstm_step<<<128, 256>>>(out, t);
    }
}

// round 9
// speedup vs baseline: 2.1628x; 2.1628x over previous
#include <cuda_runtime.h>
#include <cuda_bf16.h>
#include <cstdint>

#define TB 64
#define FF 256
#define TT 512
#define HH 1024

// Column packing: logical gate-column (g, n) with n = jj*8 + r  ->  PC = jj*32 + g*8 + r.
// P2 CTA jj (0..127) owns PC in [32jj, 32jj+32) = all 4 gates for n in [8jj, 8jj+8).

// ---------------- device scratch ----------------
__device__ uint4 g_hA  [2][16384];          // h A-fragments, ping-pong: idx4 = k8*128 + mtile*32 + lane
__device__ uint4 g_xinA[4194304];           // xin A-frags: idx4 = ((t*64 + k8)*4 + mtile)*32 + lane  (64MB)
__device__ uint4 g_WhB [1048576];           // Wh B-frags: idx4 = (nblk*128 + k8)*32 + lane  (16MB, nblk=PC>>4)
__device__ uint4 g_WxB [524288];            // Wx B-frags: idx4 = (nblk*64  + k8)*32 + lane  (8MB)
__device__ float g_bt  [4096];              // bias in PC order
__device__ float g_gx  [(size_t)TT * 4096 * 64];   // P1 out: [t][PC][b]  (536MB)
__device__ float g_hseq[(size_t)TT * HH * 64];     // [t][n][b] (134MB)
__device__ float g_c   [TB * HH];                  // [b][n]

// Round fp32 -> tf32 (.b32 destination register required)
__device__ __forceinline__ float tf32r(float v) {
    uint32_t r;
    asm("cvt.rna.tf32.f32 %0, %1;" : "=r"(r) : "f"(v));
    return __uint_as_float(r);
}
__device__ __forceinline__ float sigf(float x) { return 1.0f / (1.0f + __expf(-x)); }

// m16n8k8 tf32 mma, fp32 accumulate in place
__device__ __forceinline__ void mma8(float* c, const uint4& a, uint32_t b0, uint32_t b1) {
    asm volatile("mma.sync.aligned.m16n8k8.row.col.f32.tf32.tf32.f32 "
                 "{%0,%1,%2,%3}, {%4,%5,%6,%7}, {%8,%9}, {%0,%1,%2,%3};"
                 : "+f"(c[0]), "+f"(c[1]), "+f"(c[2]), "+f"(c[3])
                 : "r"(a.x), "r"(a.y), "r"(a.z), "r"(a.w), "r"(b0), "r"(b1));
}

// Fragment index helpers (PTX m16n8k8 canonical layouts):
// A (16x8): lane = (row&7)*4 + (col&3), slot = ((col>>2)&1)*2 + ((row>>3)&1)
// B (8x8, col): lane = n*4 + (k&3), b0 at k<4, b1 at k>=4;
//               packed float4 = {t0b0, t0b1, t1b0, t1b1} for the two n8-tiles of an n16 block.
// C: c0,c1 at (row=g, col=2*tg+{0,1}); c2,c3 at (row=g+8, same cols).

// ---------------- prep: Wh -> B-fragments ----------------
__global__ __launch_bounds__(256) void prep_whB(const float* __restrict__ Wf, const float* __restrict__ Wi,
                                                const float* __restrict__ Wu, const float* __restrict__ Wo) {
    int gid = blockIdx.x * 256 + threadIdx.x;       // k*4096 + g*1024 + n ; 1024*4096
    int n = gid & 1023, g = (gid >> 10) & 3, k = gid >> 12;
    const float* W = (g == 0) ? Wf : (g == 1) ? Wi : (g == 2) ? Wu : Wo;
    float v = tf32r(W[(size_t)(512 + k) * HH + n]);
    int jj = n >> 3, r = n & 7;
    int PC = jj * 32 + g * 8 + r;
    int nblk = PC >> 4, pcc = PC & 15;
    int tile = pcc >> 3, gg = pcc & 7;
    int lane = gg * 4 + (k & 3);
    int slot = tile * 2 + ((k >> 2) & 1);
    ((float*)g_WhB)[(size_t)(((nblk * 128) + (k >> 3)) * 32 + lane) * 4 + slot] = v;
}

// ---------------- prep: Wx -> B-fragments ----------------
__global__ __launch_bounds__(256) void prep_wxB(const float* __restrict__ Wf, const float* __restrict__ Wi,
                                                const float* __restrict__ Wu, const float* __restrict__ Wo) {
    int gid = blockIdx.x * 256 + threadIdx.x;       // k*4096 + g*1024 + n ; 512*4096
    int n = gid & 1023, g = (gid >> 10) & 3, k = gid >> 12;
    const float* W = (g == 0) ? Wf : (g == 1) ? Wi : (g == 2) ? Wu : Wo;
    float v = tf32r(W[(size_t)k * HH + n]);
    int jj = n >> 3, r = n & 7;
    int PC = jj * 32 + g * 8 + r;
    int nblk = PC >> 4, pcc = PC & 15;
    int tile = pcc >> 3, gg = pcc & 7;
    int lane = gg * 4 + (k & 3);
    int slot = tile * 2 + ((k >> 2) & 1);
    ((float*)g_WxB)[(size_t)(((nblk * 64) + (k >> 3)) * 32 + lane) * 4 + slot] = v;
}

// ---------------- prep: xin -> A-fragments ----------------
__global__ __launch_bounds__(256) void prep_xinA(const float* __restrict__ x, const float* __restrict__ y) {
    int gid = blockIdx.x * 256 + threadIdx.x;       // (t*64 + b)*64 + k8 ; 512*64*64
    int k8 = gid & 63, b = (gid >> 6) & 63, t = gid >> 12;
    int mtile = b >> 4;
    size_t base4 = (size_t)(((t * 64 + k8) * 4) + mtile) * 32;
#pragma unroll
    for (int i = 0; i < 8; i++) {
        int kk = k8 * 8 + i;        // 0..511
        int f = kk >> 1;
        float v = (kk & 1) ? ((t > 0) ? y[(size_t)(b * FF + f) * TT + t - 1] : 0.0f)
                           : x[(size_t)(b * FF + f) * TT + t];
        int lane = (b & 7) * 4 + (kk & 3);
        int slot = ((kk >> 2) & 1) * 2 + ((b >> 3) & 1);
        ((float*)g_xinA)[(base4 + lane) * 4 + slot] = tf32r(v);
    }
}

// ---------------- prep: bias (PC order), zero h-frags + c ----------------
__global__ __launch_bounds__(256) void prep_misc(const float* __restrict__ bf_, const float* __restrict__ bi,
                                                 const float* __restrict__ bu, const float* __restrict__ bo) {
    int gid = blockIdx.x * 256 + threadIdx.x;       // 65536
    if (gid < 16384) g_hA[0][gid] = make_uint4(0, 0, 0, 0);
    if (gid < TB * HH) g_c[gid] = 0.0f;
    if (gid < 4096) {
        int jj = gid >> 5, w5 = gid & 31;
        int g = w5 >> 3, r = w5 & 7;
        const float* bb = (g == 0) ? bf_ : (g == 1) ? bi : (g == 2) ? bu : bo;
        g_bt[gid] = bb[jj * 8 + r];
    }
}

// ---------------- P1: gx = xin @ Wx + b.  grid (32, 512), 256 thr ----------------
// CTA (j1, t): rows = 64 batch, cols = PC in [128 j1, 128 j1+128). Warp (mi, nw): m32 x n32.
__global__ __launch_bounds__(256) void p1_mma() {
    __shared__ float Ps[128][66];
    const int tid = threadIdx.x, w = tid >> 5, lane = tid & 31;
    const int j1 = blockIdx.x, t = blockIdx.y;
    const int mi = w & 1, nw = w >> 1;              // mi: m-half, nw: 0..3
    float acc[2][4][4];
#pragma unroll
    for (int a = 0; a < 2; a++)
#pragma unroll
        for (int bq = 0; bq < 4; bq++)
#pragma unroll
            for (int cq = 0; cq < 4; cq++) acc[a][bq][cq] = 0.0f;

    const size_t aBase = (size_t)t * 64 * 128 + mi * 64 + lane;
    const size_t b0Base = (size_t)(j1 * 8 + nw * 2) * 64 * 32 + lane;
    const size_t b1Base = b0Base + (size_t)64 * 32;
#pragma unroll 2
    for (int k = 0; k < 64; k++) {
        uint4 a0 = g_xinA[aBase + k * 128];
        uint4 a1 = g_xinA[aBase + k * 128 + 32];
        uint4 b0 = g_WxB[b0Base + k * 32];
        uint4 b1 = g_WxB[b1Base + k * 32];
        mma8(acc[0][0], a0, b0.x, b0.y); mma8(acc[0][1], a0, b0.z, b0.w);
        mma8(acc[0][2], a0, b1.x, b1.y); mma8(acc[0][3], a0, b1.z, b1.w);
        mma8(acc[1][0], a1, b0.x, b0.y); mma8(acc[1][1], a1, b0.z, b0.w);
        mma8(acc[1][2], a1, b1.x, b1.y); mma8(acc[1][3], a1, b1.z, b1.w);
    }
    const int g = lane >> 2, tg = lane & 3;
#pragma unroll
    for (int tm = 0; tm < 2; tm++)
#pragma unroll
        for (int tn = 0; tn < 4; tn++) {
            int rb = mi * 32 + tm * 16 + g;
            int cb = nw * 32 + tn * 8 + 2 * tg;
            Ps[cb][rb]         = acc[tm][tn][0];
            Ps[cb + 1][rb]     = acc[tm][tn][1];
            Ps[cb][rb + 8]     = acc[tm][tn][2];
            Ps[cb + 1][rb + 8] = acc[tm][tn][3];
        }
    __syncthreads();
    float* gxp = g_gx + ((size_t)t * 4096 + j1 * 128) * 64;
    for (int i = tid; i < 8192; i += 256) {
        int pcl = i >> 6, b = i & 63;
        gxp[(size_t)pcl * 64 + b] = Ps[pcl][b] + g_bt[j1 * 128 + pcl];
    }
}

// ---------------- P2: one LSTM step.  grid 128, 256 thr ----------------
// CTA jj: rows 64 batch, cols PC in [32jj, 32jj+32). Warp (kh, mw, nbw): K-half, m32, n16.
__global__ __launch_bounds__(256) void lstm_step(int t) {
    __shared__ float Ps[2][32][66];
    const int tid = threadIdx.x, w = tid >> 5, lane = tid & 31;
    const int jj = blockIdx.x;
    const int kh = w & 1, mw = (w >> 1) & 1, nbw = w >> 2;
    const int par = t & 1;
    float acc[2][2][4];
#pragma unroll
    for (int a = 0; a < 2; a++)
#pragma unroll
        for (int bq = 0; bq < 2; bq++)
#pragma unroll
            for (int cq = 0; cq < 4; cq++) acc[a][bq][cq] = 0.0f;

    const uint4* __restrict__ A = g_hA[par];
    const size_t aOff = mw * 64 + lane;
    const size_t bBase = (size_t)(jj * 2 + nbw) * 128 * 32 + lane;
#pragma unroll 2
    for (int kk = 0; kk < 64; kk++) {
        int k = kh * 64 + kk;
        uint4 a0 = A[(size_t)k * 128 + aOff];
        uint4 a1 = A[(size_t)k * 128 + aOff + 32];
        uint4 b  = g_WhB[bBase + (size_t)k * 32];
        mma8(acc[0][0], a0, b.x, b.y); mma8(acc[0][1], a0, b.z, b.w);
        mma8(acc[1][0], a1, b.x, b.y); mma8(acc[1][1], a1, b.z, b.w);
    }
    const int g = lane >> 2, tg = lane & 3;
#pragma unroll
    for (int tm = 0; tm < 2; tm++)
#pragma unroll
        for (int tn = 0; tn < 2; tn++) {
            int rb = mw * 32 + tm * 16 + g;
            int cb = nbw * 16 + tn * 8 + 2 * tg;
            Ps[kh][cb][rb]         = acc[tm][tn][0];
            Ps[kh][cb + 1][rb]     = acc[tm][tn][1];
            Ps[kh][cb][rb + 8]     = acc[tm][tn][2];
            Ps[kh][cb + 1][rb + 8] = acc[tm][tn][3];
        }
    __syncthreads();

    const float* gxp = g_gx + ((size_t)t * 4096 + jj * 32) * 64;
    float* hAn = (float*)g_hA[par ^ 1];
#pragma unroll
    for (int it = 0; it < 2; it++) {
        int idx = tid + it * 256;               // 512 cells: r in [0,8), b in [0,64)
        int r = idx >> 6, b = idx & 63;
        float p[4];
#pragma unroll
        for (int gg = 0; gg < 4; gg++) {
            int pcl = gg * 8 + r;
            p[gg] = Ps[0][pcl][b] + Ps[1][pcl][b] + gxp[(size_t)pcl * 64 + b];
        }
        float ff = sigf(p[0]), ii = sigf(p[1]), uu = tanhf(p[2]), oo = sigf(p[3]);
        int n = jj * 8 + r;
        int ci = b * HH + n;
        float cn = g_c[ci] * ff + ii * uu;
        g_c[ci] = cn;
        float h = oo * tanhf(cn);
        g_hseq[((size_t)t * HH + n) * 64 + b] = h;
        // scatter tf32-rounded h into next step's A-fragment image (k8 = n>>3 = jj)
        int lane2 = (b & 7) * 4 + (r & 3);
        int slot  = ((r >> 2) & 1) * 2 + ((b >> 3) & 1);
        int mtile = b >> 4;
        hAn[(size_t)(jj * 128 + mtile * 32 + lane2) * 4 + slot] = tf32r(h);
    }
}

// ---------------- finalize: transpose h_seq -> out[b][n][t]; copy c_fin ----------------
__global__ __launch_bounds__(256) void finalize(float* __restrict__ out) {
    __shared__ float tile[64][65];
    int n = blockIdx.x, t0 = blockIdx.y * 64;
    int tid = threadIdx.x;
    for (int i = tid; i < 4096; i += 256) {
        int tt = i >> 6, b = i & 63;
        tile[tt][b] = g_hseq[((size_t)(t0 + tt) * HH + n) * 64 + b];
    }
    __syncthreads();
    for (int i = tid; i < 4096; i += 256) {
        int b = i >> 6, tt = i & 63;
        out[((size_t)b * HH + n) * TT + t0 + tt] = tile[tt][b];
    }
}
__global__ __launch_bounds__(256) void copy_c(float* __restrict__ out) {
    int i = blockIdx.x * 256 + threadIdx.x;
    if (i < TB * HH) out[(size_t)TB * HH * TT + i] = g_c[i];
}

// ---------------- launch ----------------
extern "C" void kernel_launch(void* const* d_in, const int* in_sizes, int n_in,
                              void* d_out, int out_size) {
    const float* x   = (const float*)d_in[0];
    const float* y   = (const float*)d_in[1];
    // d_in[2] = subject_id (unused in 'none' mode)
    const float* Wf  = (const float*)d_in[3];
    const float* bf_ = (const float*)d_in[4];
    const float* Wi  = (const float*)d_in[5];
    const float* bi  = (const float*)d_in[6];
    const float* Wu  = (const float*)d_in[7];
    const float* bu  = (const float*)d_in[8];
    const float* Wo  = (const float*)d_in[9];
    const float* bo  = (const float*)d_in[10];
    float* out = (float*)d_out;

    prep_whB <<<16384, 256>>>(Wf, Wi, Wu, Wo);
    prep_wxB <<<8192, 256>>>(Wf, Wi, Wu, Wo);
    prep_xinA<<<8192, 256>>>(x, y);
    prep_misc<<<256, 256>>>(bf_, bi, bu, bo);

    p1_mma<<<dim3(32, 512), 256>>>();

    for (int t = 0; t < TT; t++)
        lstm_step<<<128, 256>>>(t);

    finalize<<<dim3(HH, TT / 64), 256>>>(out);
    copy_c<<<256, 256>>>(out);
}

// round 10
// speedup vs baseline: 4.4841x; 2.0733x over previous
#include <cuda_runtime.h>
#include <cuda_bf16.h>
#include <cstdint>

#define TB 64
#define FF 256
#define TT 512
#define HH 1024

// Column packing: (g, n) with n = jj*8 + r  ->  PC = jj*32 + g*8 + r.
// P2 CTA jj (0..127) owns PC in [32jj, 32jj+32) = all 4 gates for n in [8jj, 8jj+8).

// ---------------- device scratch ----------------
__device__ uint4 g_hA  [2][16384];          // h A-fragments ping-pong: idx4 = k8*128 + mtile*32 + lane
__device__ uint4 g_xinA[4194304];           // xin A-frags: idx4 = ((t*64 + k8)*4 + mtile)*32 + lane
__device__ uint4 g_WhB [1048576];           // Wh B-frags: idx4 = (nblk*128 + k8)*32 + lane (nblk = jj*2+nbw)
__device__ uint4 g_WxB [524288];            // Wx B-frags: idx4 = (nblk*64  + k8)*32 + lane
__device__ float g_bt  [4096];              // bias in PC order
__device__ float g_gx  [(size_t)TT * 4096 * 64];   // P1 out: [t][PC][b]
__device__ float g_hseq[(size_t)TT * HH * 64];     // [t][n][b]
__device__ float g_c   [TB * HH];                  // [b][n]
__device__ unsigned g_arrive;                      // grid-barrier counter (reset each launch)

__device__ __forceinline__ float tf32r(float v) {
    uint32_t r;
    asm("cvt.rna.tf32.f32 %0, %1;" : "=r"(r) : "f"(v));
    return __uint_as_float(r);
}
__device__ __forceinline__ float sigf(float x) { return 1.0f / (1.0f + __expf(-x)); }

__device__ __forceinline__ void mma8(float* c, const uint4& a, uint32_t b0, uint32_t b1) {
    asm volatile("mma.sync.aligned.m16n8k8.row.col.f32.tf32.tf32.f32 "
                 "{%0,%1,%2,%3}, {%4,%5,%6,%7}, {%8,%9}, {%0,%1,%2,%3};"
                 : "+f"(c[0]), "+f"(c[1]), "+f"(c[2]), "+f"(c[3])
                 : "r"(a.x), "r"(a.y), "r"(a.z), "r"(a.w), "r"(b0), "r"(b1));
}

// Fragment layouts (PTX m16n8k8): A lane=(row&7)*4+(col&3), slot=((col>>2)&1)*2+((row>>3)&1);
// B lane=n*4+(k&3), float4={t0b0,t0b1,t1b0,t1b1} per n16; C cols 2*tg+{0,1}, rows g/g+8.

// ---------------- prep: Wh -> B-fragments ----------------
__global__ __launch_bounds__(256) void prep_whB(const float* __restrict__ Wf, const float* __restrict__ Wi,
                                                const float* __restrict__ Wu, const float* __restrict__ Wo) {
    int gid = blockIdx.x * 256 + threadIdx.x;
    int n = gid & 1023, g = (gid >> 10) & 3, k = gid >> 12;
    const float* W = (g == 0) ? Wf : (g == 1) ? Wi : (g == 2) ? Wu : Wo;
    float v = tf32r(W[(size_t)(512 + k) * HH + n]);
    int jj = n >> 3, r = n & 7;
    int PC = jj * 32 + g * 8 + r;
    int nblk = PC >> 4, pcc = PC & 15;
    int tile = pcc >> 3, gg = pcc & 7;
    int lane = gg * 4 + (k & 3);
    int slot = tile * 2 + ((k >> 2) & 1);
    ((float*)g_WhB)[(size_t)(((nblk * 128) + (k >> 3)) * 32 + lane) * 4 + slot] = v;
}

// ---------------- prep: Wx -> B-fragments ----------------
__global__ __launch_bounds__(256) void prep_wxB(const float* __restrict__ Wf, const float* __restrict__ Wi,
                                                const float* __restrict__ Wu, const float* __restrict__ Wo) {
    int gid = blockIdx.x * 256 + threadIdx.x;
    int n = gid & 1023, g = (gid >> 10) & 3, k = gid >> 12;
    const float* W = (g == 0) ? Wf : (g == 1) ? Wi : (g == 2) ? Wu : Wo;
    float v = tf32r(W[(size_t)k * HH + n]);
    int jj = n >> 3, r = n & 7;
    int PC = jj * 32 + g * 8 + r;
    int nblk = PC >> 4, pcc = PC & 15;
    int tile = pcc >> 3, gg = pcc & 7;
    int lane = gg * 4 + (k & 3);
    int slot = tile * 2 + ((k >> 2) & 1);
    ((float*)g_WxB)[(size_t)(((nblk * 64) + (k >> 3)) * 32 + lane) * 4 + slot] = v;
}

// ---------------- prep: xin -> A-fragments ----------------
__global__ __launch_bounds__(256) void prep_xinA(const float* __restrict__ x, const float* __restrict__ y) {
    int gid = blockIdx.x * 256 + threadIdx.x;
    int k8 = gid & 63, b = (gid >> 6) & 63, t = gid >> 12;
    int mtile = b >> 4;
    size_t base4 = (size_t)(((t * 64 + k8) * 4) + mtile) * 32;
#pragma unroll
    for (int i = 0; i < 8; i++) {
        int kk = k8 * 8 + i;
        int f = kk >> 1;
        float v = (kk & 1) ? ((t > 0) ? y[(size_t)(b * FF + f) * TT + t - 1] : 0.0f)
                           : x[(size_t)(b * FF + f) * TT + t];
        int lane = (b & 7) * 4 + (kk & 3);
        int slot = ((kk >> 2) & 1) * 2 + ((b >> 3) & 1);
        ((float*)g_xinA)[(base4 + lane) * 4 + slot] = tf32r(v);
    }
}

// ---------------- prep: bias, zero h-frags, reset barrier ----------------
__global__ __launch_bounds__(256) void prep_misc(const float* __restrict__ bf_, const float* __restrict__ bi,
                                                 const float* __restrict__ bu, const float* __restrict__ bo) {
    int gid = blockIdx.x * 256 + threadIdx.x;
    if (gid == 0) g_arrive = 0u;
    if (gid < 16384) g_hA[0][gid] = make_uint4(0, 0, 0, 0);
    if (gid < 4096) {
        int jj = gid >> 5, w5 = gid & 31;
        int g = w5 >> 3, r = w5 & 7;
        const float* bb = (g == 0) ? bf_ : (g == 1) ? bi : (g == 2) ? bu : bo;
        g_bt[gid] = bb[jj * 8 + r];
    }
}

// ---------------- P1: gx = xin @ Wx + b.  grid (32, 512), 256 thr ----------------
__global__ __launch_bounds__(256) void p1_mma() {
    __shared__ float Ps[128][66];
    const int tid = threadIdx.x, w = tid >> 5, lane = tid & 31;
    const int j1 = blockIdx.x, t = blockIdx.y;
    const int mi = w & 1, nw = w >> 1;
    float acc[2][4][4];
#pragma unroll
    for (int a = 0; a < 2; a++)
#pragma unroll
        for (int bq = 0; bq < 4; bq++)
#pragma unroll
            for (int cq = 0; cq < 4; cq++) acc[a][bq][cq] = 0.0f;

    const size_t aBase = (size_t)t * 64 * 128 + mi * 64 + lane;
    const size_t b0Base = (size_t)(j1 * 8 + nw * 2) * 64 * 32 + lane;
    const size_t b1Base = b0Base + (size_t)64 * 32;
#pragma unroll 2
    for (int k = 0; k < 64; k++) {
        uint4 a0 = g_xinA[aBase + k * 128];
        uint4 a1 = g_xinA[aBase + k * 128 + 32];
        uint4 b0 = g_WxB[b0Base + k * 32];
        uint4 b1 = g_WxB[b1Base + k * 32];
        mma8(acc[0][0], a0, b0.x, b0.y); mma8(acc[0][1], a0, b0.z, b0.w);
        mma8(acc[0][2], a0, b1.x, b1.y); mma8(acc[0][3], a0, b1.z, b1.w);
        mma8(acc[1][0], a1, b0.x, b0.y); mma8(acc[1][1], a1, b0.z, b0.w);
        mma8(acc[1][2], a1, b1.x, b1.y); mma8(acc[1][3], a1, b1.z, b1.w);
    }
    const int g = lane >> 2, tg = lane & 3;
#pragma unroll
    for (int tm = 0; tm < 2; tm++)
#pragma unroll
        for (int tn = 0; tn < 4; tn++) {
            int rb = mi * 32 + tm * 16 + g;
            int cb = nw * 32 + tn * 8 + 2 * tg;
            Ps[cb][rb]         = acc[tm][tn][0];
            Ps[cb + 1][rb]     = acc[tm][tn][1];
            Ps[cb][rb + 8]     = acc[tm][tn][2];
            Ps[cb + 1][rb + 8] = acc[tm][tn][3];
        }
    __syncthreads();
    float* gxp = g_gx + ((size_t)t * 4096 + j1 * 128) * 64;
    for (int i = tid; i < 8192; i += 256) {
        int pcl = i >> 6, b = i & 63;
        gxp[(size_t)pcl * 64 + b] = Ps[pcl][b] + g_bt[j1 * 128 + pcl];
    }
}

// ---------------- P2: persistent LSTM. grid 128 (co-resident), 256 thr ----------------
// CTA jj owns PC [32jj, 32jj+32). Warp (kh, mq): K-half x m16 tile; computes full n32.
// Wh slice resident in smem; c resident in smem; one grid barrier per step.
__global__ __launch_bounds__(256) void lstm_persist() {
    extern __shared__ uint4 smemB[];        // 8192 uint4 = 128KB : [nbw(2)][k8(128)][lane(32)]
    __shared__ float Ps[2][32][66];
    __shared__ float c_s[512];              // [r(8)][b(64)]
    const int tid = threadIdx.x, w = tid >> 5, lane = tid & 31;
    const int jj = blockIdx.x;
    const int kh = w & 1, mq = w >> 1;      // kh: K-half, mq: m16 tile 0..3
    const int g = lane >> 2, tg = lane & 3;

    {   // load Wh slice into smem once
        const uint4* src = g_WhB + (size_t)jj * 2 * 128 * 32;
        for (int i = tid; i < 8192; i += 256) smemB[i] = src[i];
    }
    for (int i = tid; i < 512; i += 256) c_s[i] = 0.0f;
    __syncthreads();

    for (int t = 0; t < TT; t++) {
        const int par = t & 1;
        // prefetch gx tile (independent of h): gxr[i] = gx[tid + i*256]
        float gxr[8];
        const float* gxp = g_gx + ((size_t)t * 4096 + jj * 32) * 64;
#pragma unroll
        for (int i = 0; i < 8; i++) gxr[i] = gxp[tid + i * 256];

        float acc[2][2][4];
#pragma unroll
        for (int a = 0; a < 2; a++)
#pragma unroll
            for (int bq = 0; bq < 2; bq++)
#pragma unroll
                for (int cq = 0; cq < 4; cq++) acc[a][bq][cq] = 0.0f;

        const uint4* __restrict__ A = g_hA[par];
#pragma unroll 4
        for (int kk = 0; kk < 64; kk++) {
            int k = kh * 64 + kk;
            uint4 a  = A[(size_t)k * 128 + mq * 32 + lane];
            uint4 b0 = smemB[k * 32 + lane];
            uint4 b1 = smemB[4096 + k * 32 + lane];
            mma8(acc[0][0], a, b0.x, b0.y); mma8(acc[0][1], a, b0.z, b0.w);
            mma8(acc[1][0], a, b1.x, b1.y); mma8(acc[1][1], a, b1.z, b1.w);
        }
#pragma unroll
        for (int nb = 0; nb < 2; nb++)
#pragma unroll
            for (int tn = 0; tn < 2; tn++) {
                int rb = mq * 16 + g;
                int cb = nb * 16 + tn * 8 + 2 * tg;
                Ps[kh][cb][rb]         = acc[nb][tn][0];
                Ps[kh][cb + 1][rb]     = acc[nb][tn][1];
                Ps[kh][cb][rb + 8]     = acc[nb][tn][2];
                Ps[kh][cb + 1][rb + 8] = acc[nb][tn][3];
            }
        __syncthreads();

        // epilogue: 512 cells, 2 per thread
        float* hAn = (float*)g_hA[par ^ 1];
#pragma unroll
        for (int it = 0; it < 2; it++) {
            int idx = tid + it * 256;
            int r = idx >> 6, b = idx & 63;
            float p[4];
#pragma unroll
            for (int gg = 0; gg < 4; gg++) {
                int pcl = gg * 8 + r;
                p[gg] = Ps[0][pcl][b] + Ps[1][pcl][b] + gxr[2 * gg + it];
            }
            float ff = sigf(p[0]), ii = sigf(p[1]), uu = tanhf(p[2]), oo = sigf(p[3]);
            float cn = c_s[idx] * ff + ii * uu;
            c_s[idx] = cn;
            float h = oo * tanhf(cn);
            int n = jj * 8 + r;
            g_hseq[((size_t)t * HH + n) * 64 + b] = h;
            int lane2 = (b & 7) * 4 + (r & 3);
            int slot  = ((r >> 2) & 1) * 2 + ((b >> 3) & 1);
            int mtile = b >> 4;
            hAn[(size_t)(jj * 128 + mtile * 32 + lane2) * 4 + slot] = tf32r(h);
        }

        // grid barrier (monotone counter; all 128 CTAs co-resident)
        __threadfence();
        __syncthreads();
        if (tid == 0) {
            atomicAdd(&g_arrive, 1u);
            unsigned target = 128u * (unsigned)(t + 1);
            while (*(volatile unsigned*)&g_arrive < target) { }
            __threadfence();
        }
        __syncthreads();
    }

    // write c_fin
    for (int i = tid; i < 512; i += 256) {
        int r = i >> 6, b = i & 63;
        g_c[b * HH + jj * 8 + r] = c_s[i];
    }
}

// ---------------- finalize: transpose h_seq -> out[b][n][t]; copy c_fin ----------------
__global__ __launch_bounds__(256) void finalize(float* __restrict__ out) {
    __shared__ float tile[64][65];
    int n = blockIdx.x, t0 = blockIdx.y * 64;
    int tid = threadIdx.x;
    for (int i = tid; i < 4096; i += 256) {
        int tt = i >> 6, b = i & 63;
        tile[tt][b] = g_hseq[((size_t)(t0 + tt) * HH + n) * 64 + b];
    }
    __syncthreads();
    for (int i = tid; i < 4096; i += 256) {
        int b = i >> 6, tt = i & 63;
        out[((size_t)b * HH + n) * TT + t0 + tt] = tile[tt][b];
    }
}
__global__ __launch_bounds__(256) void copy_c(float* __restrict__ out) {
    int i = blockIdx.x * 256 + threadIdx.x;
    if (i < TB * HH) out[(size_t)TB * HH * TT + i] = g_c[i];
}

// ---------------- launch ----------------
extern "C" void kernel_launch(void* const* d_in, const int* in_sizes, int n_in,
                              void* d_out, int out_size) {
    const float* x   = (const float*)d_in[0];
    const float* y   = (const float*)d_in[1];
    // d_in[2] = subject_id (unused in 'none' mode)
    const float* Wf  = (const float*)d_in[3];
    const float* bf_ = (const float*)d_in[4];
    const float* Wi  = (const float*)d_in[5];
    const float* bi  = (const float*)d_in[6];
    const float* Wu  = (const float*)d_in[7];
    const float* bu  = (const float*)d_in[8];
    const float* Wo  = (const float*)d_in[9];
    const float* bo  = (const float*)d_in[10];
    float* out = (float*)d_out;

    cudaFuncSetAttribute(lstm_persist, cudaFuncAttributeMaxDynamicSharedMemorySize, 131072);

    prep_whB <<<16384, 256>>>(Wf, Wi, Wu, Wo);
    prep_wxB <<<8192, 256>>>(Wf, Wi, Wu, Wo);
    prep_xinA<<<8192, 256>>>(x, y);
    prep_misc<<<256, 256>>>(bf_, bi, bu, bo);

    p1_mma<<<dim3(32, 512), 256>>>();

    lstm_persist<<<128, 256, 131072>>>();

    finalize<<<dim3(HH, TT / 64), 256>>>(out);
    copy_c<<<256, 256>>>(out);
}